// round 11
// baseline (speedup 1.0000x reference)
#include <cuda_runtime.h>

#define B 4
#define C 19
#define H 192
#define W 192
#define HW (H*W)
// 40 * log2(e): exp(-40*x) == exp2(-THC*x)
#define THC 57.70780163555853f
#define SEG 6          // elements per lane; 32*6 = 192 = chain length
#define TW 32          // column-tile width
#define NCT 456        // col tiles = B*C*(W/TW)

// ---------------------------------------------------------------------------
// Static scratch (allocations forbidden)
// ---------------------------------------------------------------------------
__device__ float g_zc  [B*HW];                 // column Z (incl diag), edge-only
__device__ float g_zr  [B*HW];                 // row Z (diag removed), edge-only
__device__ float g_colA[(size_t)B*C*HW];       // column aggregation result
__device__ float g_featA[(size_t)B*C*HW];      // ping
__device__ float g_featB[(size_t)B*C*HW];      // pong

__device__ __forceinline__ const float* pick_src(int s, const float* ext) {
    return s == 0 ? ext : (s == 1 ? g_featA : g_featB);
}

// warp scans of segment transfer (A, F): f_out = A*f_in + F
__device__ __forceinline__ void wscan_fwd(float& A, float& F, int lane) {
    #pragma unroll
    for (int dl = 1; dl < 32; dl <<= 1) {
        float oa = __shfl_up_sync(0xffffffffu, A, dl);
        float of = __shfl_up_sync(0xffffffffu, F, dl);
        if (lane >= dl) { F = fmaf(of, A, F); A = oa * A; }
    }
}
__device__ __forceinline__ void wscan_bwd(float& A, float& G, int lane) {
    #pragma unroll
    for (int dl = 1; dl < 32; dl <<= 1) {
        float oa = __shfl_down_sync(0xffffffffu, A, dl);
        float og = __shfl_down_sync(0xffffffffu, G, dl);
        if (lane < 32 - dl) { G = fmaf(A, og, G); A = oa * A; }
    }
}

// ---------------------------------------------------------------------------
// Column tile body. PDL: edge->ds prologue runs BEFORE the grid-dependency
// sync; caller syncs, then we load x and proceed.
// ---------------------------------------------------------------------------
__device__ __forceinline__ void col_prologue(int b, int j0,
                                             const float* __restrict__ edge,
                                             float* ds) {
    const int tid = threadIdx.x;
    const int lane = tid & 31, wid = tid >> 5;
    const float* eg = edge + b * HW + j0;
    #pragma unroll 4
    for (int i = wid; i < H; i += 8) {
        int sw = i * TW + (lane ^ (i & 31));
        ds[sw] = exp2f(-THC * fmaxf(eg[i * W + lane], 0.f));
    }
}

__device__ __forceinline__ void col_tile_body(int b, int c, int j0,
                                              const float* __restrict__ xg,
                                              float* xs, float* ds) {
    const int tid = threadIdx.x;
    const int lane = tid & 31, wid = tid >> 5;

    #pragma unroll 4
    for (int i = wid; i < H; i += 8) {
        int sw = i * TW + (lane ^ (i & 31));
        xs[sw] = xg[(size_t)i * W + lane];
    }
    __syncthreads();

    #pragma unroll
    for (int cc = 0; cc < 4; ++cc) {
        const int jl = wid * 4 + cc;
        float x[SEG], d[SEG];
        #pragma unroll
        for (int k = 0; k < SEG; ++k) {
            int i = lane * SEG + k;
            int sw = i * TW + (jl ^ (i & 31));
            x[k] = xs[sw]; d[k] = ds[sw];
        }

        float F = 0.f, A = 1.f;
        #pragma unroll
        for (int k = 0; k < SEG; ++k) { F = fmaf(F, d[k], x[k]); A *= d[k]; }
        float Af = A;
        wscan_fwd(Af, F, lane);
        float fin = __shfl_up_sync(0xffffffffu, F, 1);
        if (lane == 0) fin = 0.f;
        float f[SEG], v = fin;
        #pragma unroll
        for (int k = 0; k < SEG; ++k) { v = fmaf(v, d[k], x[k]); f[k] = v; }

        float G = 0.f, Ab = A;
        #pragma unroll
        for (int k = SEG - 1; k >= 0; --k) G = (G + x[k]) * d[k];
        wscan_bwd(Ab, G, lane);
        float gin = __shfl_down_sync(0xffffffffu, G, 1);
        if (lane == 31) gin = 0.f;

        float g = gin;
        #pragma unroll
        for (int k = SEG - 1; k >= 0; --k) {
            int i = lane * SEG + k;
            xs[i * TW + (jl ^ (i & 31))] = f[k] + g;
            g = (g + x[k]) * d[k];
        }
    }
    __syncthreads();

    float* ag = g_colA + ((size_t)(b * C + c) * H) * W + j0;
    #pragma unroll 4
    for (int i = wid; i < H; i += 8) {
        int sw = i * TW + (lane ^ (i & 31));
        ag[(size_t)i * W + lane] = xs[sw];
    }
}

// ---------------------------------------------------------------------------
// zc tile: (b, j-tile) ones-scan along columns (edge-only)
// ---------------------------------------------------------------------------
__device__ __forceinline__ void zc_tile_body(int b, int j0, float* xs, float* ds) {
    const int tid = threadIdx.x;
    const int lane = tid & 31, wid = tid >> 5;
    __syncthreads();          // ds staged by col_prologue

    #pragma unroll
    for (int cc = 0; cc < 4; ++cc) {
        const int jl = wid * 4 + cc;
        float d[SEG];
        #pragma unroll
        for (int k = 0; k < SEG; ++k) {
            int i = lane * SEG + k;
            d[k] = ds[i * TW + (jl ^ (i & 31))];
        }
        float F = 0.f, A = 1.f;
        #pragma unroll
        for (int k = 0; k < SEG; ++k) { F = fmaf(F, d[k], 1.f); A *= d[k]; }
        float Af = A;
        wscan_fwd(Af, F, lane);
        float fin = __shfl_up_sync(0xffffffffu, F, 1);
        if (lane == 0) fin = 0.f;
        float f[SEG], v = fin;
        #pragma unroll
        for (int k = 0; k < SEG; ++k) { v = fmaf(v, d[k], 1.f); f[k] = v; }

        float G = 0.f, Ab = A;
        #pragma unroll
        for (int k = SEG - 1; k >= 0; --k) G = (G + 1.f) * d[k];
        wscan_bwd(Ab, G, lane);
        float gin = __shfl_down_sync(0xffffffffu, G, 1);
        if (lane == 31) gin = 0.f;

        float g = gin;
        #pragma unroll
        for (int k = SEG - 1; k >= 0; --k) {
            int i = lane * SEG + k;
            xs[i * TW + (jl ^ (i & 31))] = f[k] + g;   // zc incl diag
            g = (g + 1.f) * d[k];
        }
    }
    __syncthreads();

    float* zg = g_zc + b * HW + j0;
    #pragma unroll 4
    for (int i = wid; i < H; i += 8) {
        int sw = i * TW + (lane ^ (i & 31));
        zg[i * W + lane] = xs[sw];
    }
}

// ---------------------------------------------------------------------------
// zr chain: edge-only ones-scan along a row (coalesced)
// ---------------------------------------------------------------------------
__device__ __forceinline__ void zr_chain(int b, int i, int lane,
                                         const float* __restrict__ edge) {
    size_t ro = (size_t)b * HW + (size_t)i * W + lane * SEG;
    const float2* ep = (const float2*)(edge + ro);
    float d[SEG];
    #pragma unroll
    for (int k = 0; k < SEG / 2; ++k) {
        float2 t = ep[k];
        d[2*k]   = exp2f(-THC * fmaxf(t.x, 0.f));
        d[2*k+1] = exp2f(-THC * fmaxf(t.y, 0.f));
    }
    float F = 0.f, A = 1.f;
    #pragma unroll
    for (int k = 0; k < SEG; ++k) { F = fmaf(F, d[k], 1.f); A *= d[k]; }
    float Af = A;
    wscan_fwd(Af, F, lane);
    float fin = __shfl_up_sync(0xffffffffu, F, 1);
    if (lane == 0) fin = 0.f;
    float f[SEG], v = fin;
    #pragma unroll
    for (int k = 0; k < SEG; ++k) { v = fmaf(v, d[k], 1.f); f[k] = v; }

    float G = 0.f, Ab = A;
    #pragma unroll
    for (int k = SEG - 1; k >= 0; --k) G = (G + 1.f) * d[k];
    wscan_bwd(Ab, G, lane);
    float gin = __shfl_down_sync(0xffffffffu, G, 1);
    if (lane == 31) gin = 0.f;

    float o[SEG], g = gin;
    #pragma unroll
    for (int k = SEG - 1; k >= 0; --k) {
        o[k] = f[k] + g - 1.f;                 // diag removed
        g = (g + 1.f) * d[k];
    }
    float2* zp = (float2*)(g_zr + ro);
    #pragma unroll
    for (int k = 0; k < SEG / 2; ++k) zp[k] = make_float2(o[2*k], o[2*k+1]);
}

// ---------------------------------------------------------------------------
// K1: iter-1 column kernel (first in chain; no upstream dependency)
// grid 456+24+24: col tiles | zc tiles | zr groups
// ---------------------------------------------------------------------------
__global__ __launch_bounds__(256) void k_col1(const float* __restrict__ mask,
                                              const float* __restrict__ edge) {
    __shared__ float sm[2 * H * TW];
    float* xs = sm;
    float* ds = sm + H * TW;

    const int bid = blockIdx.x;
    if (bid < NCT) {
        const int jt = bid % (W / TW);
        const int c  = (bid / (W / TW)) % C;
        const int b  = bid / ((W / TW) * C);
        col_prologue(b, jt * TW, edge, ds);
        const float* xg = mask + ((size_t)(b * C + c) * H) * W + jt * TW;
        col_tile_body(b, c, jt * TW, xg, xs, ds);
    } else if (bid < NCT + 24) {
        const int u = bid - NCT;
        col_prologue(u / 6, (u % 6) * TW, edge, ds);
        zc_tile_body(u / 6, (u % 6) * TW, xs, ds);
    } else {
        const int u = bid - NCT - 24;          // [0, 24)
        const int b = u / 6;
        const int lane = threadIdx.x & 31, wid = threadIdx.x >> 5;
        #pragma unroll 1
        for (int q = 0; q < 4; ++q) {
            int i = (u % 6) * TW + wid * 4 + q;   // [0, 192)
            zr_chain(b, i, lane, edge);
        }
    }
}

// ---------------------------------------------------------------------------
// K2: column kernel for iters 2/3. PDL: edge prologue, then grid-dep sync.
// ---------------------------------------------------------------------------
__global__ __launch_bounds__(256) void k_col(const float* __restrict__ edge, int src) {
    __shared__ float sm[2 * H * TW];
    float* xs = sm;
    float* ds = sm + H * TW;

    const int bid = blockIdx.x;
    const int jt = bid % (W / TW);
    const int c  = (bid / (W / TW)) % C;
    const int b  = bid / ((W / TW) * C);

    col_prologue(b, jt * TW, edge, ds);        // independent of producer
    cudaGridDependencySynchronize();           // wait for upstream row kernel
    const float* xg = (src == 1 ? g_featA : g_featB) + ((size_t)(b * C + c) * H) * W + jt * TW;
    col_tile_body(b, c, jt * TW, xg, xs, ds);
}

// ---------------------------------------------------------------------------
// K3: row kernel. PDL: d from edge before the sync; x/colA/z after.
// ---------------------------------------------------------------------------
__global__ __launch_bounds__(128) void k_row(const float* __restrict__ xin,
                                             const float* __restrict__ edge,
                                             float* __restrict__ oext,
                                             int src, int dst) {
    const int ch = blockIdx.x * 4 + (threadIdx.x >> 5);   // [0, B*C*H)
    const int lane = threadIdx.x & 31;
    int b = ch / (C * H);
    int r = ch - b * (C * H);
    int c = r / H;
    int i = r - c * H;

    size_t off = ((size_t)(b * C + c) * H + i) * W + lane * SEG;
    size_t ro  = (size_t)b * HW + (size_t)i * W + lane * SEG;

    // PDL prologue: decay from edge (kernel input, independent of producer)
    const float2* ep = (const float2*)(edge + ro);
    float d[SEG];
    #pragma unroll
    for (int k = 0; k < SEG / 2; ++k) {
        float2 t = ep[k];
        d[2*k]   = exp2f(-THC * fmaxf(t.x, 0.f));
        d[2*k+1] = exp2f(-THC * fmaxf(t.y, 0.f));
    }

    cudaGridDependencySynchronize();           // wait for upstream col kernel

    const float2* xp = (const float2*)(pick_src(src, xin) + off);
    const float2* ap = (const float2*)(g_colA + off);
    float x[SEG], a[SEG];
    #pragma unroll
    for (int k = 0; k < SEG / 2; ++k) { float2 t = xp[k]; x[2*k] = t.x; x[2*k+1] = t.y; }
    #pragma unroll
    for (int k = 0; k < SEG / 2; ++k) { float2 t = ap[k]; a[2*k] = t.x; a[2*k+1] = t.y; }

    float F = 0.f, A = 1.f;
    #pragma unroll
    for (int k = 0; k < SEG; ++k) { F = fmaf(F, d[k], x[k]); A *= d[k]; }
    float Af = A;
    wscan_fwd(Af, F, lane);
    float fin = __shfl_up_sync(0xffffffffu, F, 1);
    if (lane == 0) fin = 0.f;
    float f[SEG], v = fin;
    #pragma unroll
    for (int k = 0; k < SEG; ++k) { v = fmaf(v, d[k], x[k]); f[k] = v; }

    float G = 0.f, Ab = A;
    #pragma unroll
    for (int k = SEG - 1; k >= 0; --k) G = (G + x[k]) * d[k];
    wscan_bwd(Ab, G, lane);
    float gin = __shfl_down_sync(0xffffffffu, G, 1);
    if (lane == 31) gin = 0.f;

    const float2* zcp = (const float2*)(g_zc + ro);
    const float2* zrp = (const float2*)(g_zr + ro);
    float z[SEG];
    #pragma unroll
    for (int k = 0; k < SEG / 2; ++k) {
        float2 tc = zcp[k], tr = zrp[k];
        z[2*k]   = __fdividef(1.f, tc.x + tr.x);
        z[2*k+1] = __fdividef(1.f, tc.y + tr.y);
    }

    float o[SEG], g = gin;
    #pragma unroll
    for (int k = SEG - 1; k >= 0; --k) {
        o[k] = (a[k] + f[k] + g - x[k]) * z[k];
        g = (g + x[k]) * d[k];
    }

    float* ob = (dst == 0) ? oext : (dst == 1 ? g_featA : g_featB);
    float2* op = (float2*)(ob + off);
    #pragma unroll
    for (int k = 0; k < SEG / 2; ++k)
        op[k] = make_float2(o[2*k], o[2*k+1]);
}

// ---------------------------------------------------------------------------
// iter fixed at 3 by setup_inputs. 6 launches, PDL-chained.
// ---------------------------------------------------------------------------
extern "C" void kernel_launch(void* const* d_in, const int* in_sizes, int n_in,
                              void* d_out, int out_size) {
    const float* mask = (const float*)d_in[0];
    const float* edge = (const float*)d_in[1];
    float* out = (float*)d_out;

    const int GR = (B * C * H) / 4;     // 3648 blocks

    cudaLaunchAttribute attr[1];
    attr[0].id = cudaLaunchAttributeProgrammaticStreamSerialization;
    attr[0].val.programmaticStreamSerializationAllowed = 1;

    cudaLaunchConfig_t cfg = {};
    cfg.blockDim = {256, 1, 1};
    cfg.stream = 0;
    cfg.attrs = attr;
    cfg.numAttrs = 1;

    // iter 1 (col kernel also computes zc, zr)
    cfg.gridDim = {NCT + 48, 1, 1};
    cudaLaunchKernelEx(&cfg, k_col1, mask, edge);

    cfg.blockDim = {128, 1, 1};
    cfg.gridDim = {(unsigned)GR, 1, 1};
    cudaLaunchKernelEx(&cfg, k_row, mask, edge, (float*)nullptr, 0, 1);

    cfg.blockDim = {256, 1, 1};
    cfg.gridDim = {NCT, 1, 1};
    cudaLaunchKernelEx(&cfg, k_col, edge, 1);

    cfg.blockDim = {128, 1, 1};
    cfg.gridDim = {(unsigned)GR, 1, 1};
    cudaLaunchKernelEx(&cfg, k_row, (const float*)nullptr, edge, (float*)nullptr, 1, 2);

    cfg.blockDim = {256, 1, 1};
    cfg.gridDim = {NCT, 1, 1};
    cudaLaunchKernelEx(&cfg, k_col, edge, 2);

    cfg.blockDim = {128, 1, 1};
    cfg.gridDim = {(unsigned)GR, 1, 1};
    cudaLaunchKernelEx(&cfg, k_row, (const float*)nullptr, edge, out, 2, 0);
}

// round 12
// speedup vs baseline: 1.0084x; 1.0084x over previous
#include <cuda_runtime.h>

#define B 4
#define C 19
#define H 192
#define W 192
#define HW (H*W)
// 40 * log2(e): exp(-40*x) == exp2(-THC*x)
#define THC 57.70780163555853f
#define SEG 6          // elements per lane; 32*6 = 192 = chain length
#define TW 32          // column-tile width
#define NCT 456        // col tiles = B*C*(W/TW)
#define NPAIR 10       // channel pair-units per (b,i): 9 pairs + 1 self-pair

// ---------------------------------------------------------------------------
// Static scratch (allocations forbidden)
// ---------------------------------------------------------------------------
__device__ float g_zc  [B*HW];                 // column Z (incl diag), edge-only
__device__ float g_zr  [B*HW];                 // row Z (diag removed), edge-only
__device__ float g_colA[(size_t)B*C*HW];       // column aggregation result
__device__ float g_featA[(size_t)B*C*HW];      // ping
__device__ float g_featB[(size_t)B*C*HW];      // pong

__device__ __forceinline__ const float* pick_src(int s, const float* ext) {
    return s == 0 ? ext : (s == 1 ? g_featA : g_featB);
}

// warp scans of segment transfer (A, F): f_out = A*f_in + F
__device__ __forceinline__ void wscan_fwd(float& A, float& F, int lane) {
    #pragma unroll
    for (int dl = 1; dl < 32; dl <<= 1) {
        float oa = __shfl_up_sync(0xffffffffu, A, dl);
        float of = __shfl_up_sync(0xffffffffu, F, dl);
        if (lane >= dl) { F = fmaf(of, A, F); A = oa * A; }
    }
}
__device__ __forceinline__ void wscan_bwd(float& A, float& G, int lane) {
    #pragma unroll
    for (int dl = 1; dl < 32; dl <<= 1) {
        float oa = __shfl_down_sync(0xffffffffu, A, dl);
        float og = __shfl_down_sync(0xffffffffu, G, dl);
        if (lane < 32 - dl) { G = fmaf(A, og, G); A = oa * A; }
    }
}
// 3-payload versions: two chains share the same A (same d sequence)
__device__ __forceinline__ void wscan_fwd3(float& A, float& F0, float& F1, int lane) {
    #pragma unroll
    for (int dl = 1; dl < 32; dl <<= 1) {
        float oa = __shfl_up_sync(0xffffffffu, A, dl);
        float o0 = __shfl_up_sync(0xffffffffu, F0, dl);
        float o1 = __shfl_up_sync(0xffffffffu, F1, dl);
        if (lane >= dl) { F0 = fmaf(o0, A, F0); F1 = fmaf(o1, A, F1); A = oa * A; }
    }
}
__device__ __forceinline__ void wscan_bwd3(float& A, float& G0, float& G1, int lane) {
    #pragma unroll
    for (int dl = 1; dl < 32; dl <<= 1) {
        float oa = __shfl_down_sync(0xffffffffu, A, dl);
        float o0 = __shfl_down_sync(0xffffffffu, G0, dl);
        float o1 = __shfl_down_sync(0xffffffffu, G1, dl);
        if (lane < 32 - dl) { G0 = fmaf(A, o0, G0); G1 = fmaf(A, o1, G1); A = oa * A; }
    }
}

// ---------------------------------------------------------------------------
// d prologue for a (b, j-tile): edge -> ds (swizzled), float4 global loads
// ---------------------------------------------------------------------------
__device__ __forceinline__ void d_prologue(int b, int j0,
                                           const float* __restrict__ edge,
                                           float* ds) {
    const int tid = threadIdx.x;
    const float* eg = edge + b * HW + j0;
    #pragma unroll
    for (int it = 0; it < 6; ++it) {
        int u = it * 256 + tid;
        int row = u >> 3, g = (u & 7) << 2;
        float4 ev = *(const float4*)(eg + row * W + g);
        int rb = row & 31, s0 = row * TW;
        ds[s0 + ((g + 0) ^ rb)] = exp2f(-THC * fmaxf(ev.x, 0.f));
        ds[s0 + ((g + 1) ^ rb)] = exp2f(-THC * fmaxf(ev.y, 0.f));
        ds[s0 + ((g + 2) ^ rb)] = exp2f(-THC * fmaxf(ev.z, 0.f));
        ds[s0 + ((g + 3) ^ rb)] = exp2f(-THC * fmaxf(ev.w, 0.f));
    }
}

// ---------------------------------------------------------------------------
// Column tile body: stage x (float4), scan 4 cols/warp, write colA (float4)
// ---------------------------------------------------------------------------
__device__ __forceinline__ void col_tile_body(int b, int c, int j0,
                                              const float* __restrict__ xg,
                                              float* xs, float* ds) {
    const int tid = threadIdx.x;
    const int lane = tid & 31, wid = tid >> 5;

    #pragma unroll
    for (int it = 0; it < 6; ++it) {
        int u = it * 256 + tid;
        int row = u >> 3, g = (u & 7) << 2;
        float4 xv = *(const float4*)(xg + (size_t)row * W + g);
        int rb = row & 31, s0 = row * TW;
        xs[s0 + ((g + 0) ^ rb)] = xv.x;
        xs[s0 + ((g + 1) ^ rb)] = xv.y;
        xs[s0 + ((g + 2) ^ rb)] = xv.z;
        xs[s0 + ((g + 3) ^ rb)] = xv.w;
    }
    __syncthreads();

    #pragma unroll
    for (int cc = 0; cc < 4; ++cc) {
        const int jl = wid * 4 + cc;
        float x[SEG], d[SEG];
        #pragma unroll
        for (int k = 0; k < SEG; ++k) {
            int i = lane * SEG + k;
            int sw = i * TW + (jl ^ (i & 31));
            x[k] = xs[sw]; d[k] = ds[sw];
        }

        float F = 0.f, A = 1.f;
        #pragma unroll
        for (int k = 0; k < SEG; ++k) { F = fmaf(F, d[k], x[k]); A *= d[k]; }
        float Af = A;
        wscan_fwd(Af, F, lane);
        float fin = __shfl_up_sync(0xffffffffu, F, 1);
        if (lane == 0) fin = 0.f;
        float f[SEG], v = fin;
        #pragma unroll
        for (int k = 0; k < SEG; ++k) { v = fmaf(v, d[k], x[k]); f[k] = v; }

        float G = 0.f, Ab = A;
        #pragma unroll
        for (int k = SEG - 1; k >= 0; --k) G = (G + x[k]) * d[k];
        wscan_bwd(Ab, G, lane);
        float gin = __shfl_down_sync(0xffffffffu, G, 1);
        if (lane == 31) gin = 0.f;

        float g = gin;
        #pragma unroll
        for (int k = SEG - 1; k >= 0; --k) {
            int i = lane * SEG + k;
            xs[i * TW + (jl ^ (i & 31))] = f[k] + g;
            g = (g + x[k]) * d[k];
        }
    }
    __syncthreads();

    float* ag = g_colA + ((size_t)(b * C + c) * H) * W + j0;
    #pragma unroll
    for (int it = 0; it < 6; ++it) {
        int u = it * 256 + tid;
        int row = u >> 3, g = (u & 7) << 2;
        int rb = row & 31, s0 = row * TW;
        float4 ov;
        ov.x = xs[s0 + ((g + 0) ^ rb)];
        ov.y = xs[s0 + ((g + 1) ^ rb)];
        ov.z = xs[s0 + ((g + 2) ^ rb)];
        ov.w = xs[s0 + ((g + 3) ^ rb)];
        *(float4*)(ag + (size_t)row * W + g) = ov;
    }
}

// ---------------------------------------------------------------------------
// zc tile: ones-scan over staged ds; writeback float4
// ---------------------------------------------------------------------------
__device__ __forceinline__ void zc_tile_body(int b, int j0, float* xs, float* ds) {
    const int tid = threadIdx.x;
    const int lane = tid & 31, wid = tid >> 5;
    __syncthreads();          // ds staged by d_prologue

    #pragma unroll
    for (int cc = 0; cc < 4; ++cc) {
        const int jl = wid * 4 + cc;
        float d[SEG];
        #pragma unroll
        for (int k = 0; k < SEG; ++k) {
            int i = lane * SEG + k;
            d[k] = ds[i * TW + (jl ^ (i & 31))];
        }
        float F = 0.f, A = 1.f;
        #pragma unroll
        for (int k = 0; k < SEG; ++k) { F = fmaf(F, d[k], 1.f); A *= d[k]; }
        float Af = A;
        wscan_fwd(Af, F, lane);
        float fin = __shfl_up_sync(0xffffffffu, F, 1);
        if (lane == 0) fin = 0.f;
        float f[SEG], v = fin;
        #pragma unroll
        for (int k = 0; k < SEG; ++k) { v = fmaf(v, d[k], 1.f); f[k] = v; }

        float G = 0.f, Ab = A;
        #pragma unroll
        for (int k = SEG - 1; k >= 0; --k) G = (G + 1.f) * d[k];
        wscan_bwd(Ab, G, lane);
        float gin = __shfl_down_sync(0xffffffffu, G, 1);
        if (lane == 31) gin = 0.f;

        float g = gin;
        #pragma unroll
        for (int k = SEG - 1; k >= 0; --k) {
            int i = lane * SEG + k;
            xs[i * TW + (jl ^ (i & 31))] = f[k] + g;   // zc incl diag
            g = (g + 1.f) * d[k];
        }
    }
    __syncthreads();

    float* zg = g_zc + b * HW + j0;
    #pragma unroll
    for (int it = 0; it < 6; ++it) {
        int u = it * 256 + tid;
        int row = u >> 3, g = (u & 7) << 2;
        int rb = row & 31, s0 = row * TW;
        float4 ov;
        ov.x = xs[s0 + ((g + 0) ^ rb)];
        ov.y = xs[s0 + ((g + 1) ^ rb)];
        ov.z = xs[s0 + ((g + 2) ^ rb)];
        ov.w = xs[s0 + ((g + 3) ^ rb)];
        *(float4*)(zg + row * W + g) = ov;
    }
}

// ---------------------------------------------------------------------------
// zr chain: edge-only ones-scan along a row (coalesced)
// ---------------------------------------------------------------------------
__device__ __forceinline__ void zr_chain(int b, int i, int lane,
                                         const float* __restrict__ edge) {
    size_t ro = (size_t)b * HW + (size_t)i * W + lane * SEG;
    const float2* ep = (const float2*)(edge + ro);
    float d[SEG];
    #pragma unroll
    for (int k = 0; k < SEG / 2; ++k) {
        float2 t = ep[k];
        d[2*k]   = exp2f(-THC * fmaxf(t.x, 0.f));
        d[2*k+1] = exp2f(-THC * fmaxf(t.y, 0.f));
    }
    float F = 0.f, A = 1.f;
    #pragma unroll
    for (int k = 0; k < SEG; ++k) { F = fmaf(F, d[k], 1.f); A *= d[k]; }
    float Af = A;
    wscan_fwd(Af, F, lane);
    float fin = __shfl_up_sync(0xffffffffu, F, 1);
    if (lane == 0) fin = 0.f;
    float f[SEG], v = fin;
    #pragma unroll
    for (int k = 0; k < SEG; ++k) { v = fmaf(v, d[k], 1.f); f[k] = v; }

    float G = 0.f, Ab = A;
    #pragma unroll
    for (int k = SEG - 1; k >= 0; --k) G = (G + 1.f) * d[k];
    wscan_bwd(Ab, G, lane);
    float gin = __shfl_down_sync(0xffffffffu, G, 1);
    if (lane == 31) gin = 0.f;

    float o[SEG], g = gin;
    #pragma unroll
    for (int k = SEG - 1; k >= 0; --k) {
        o[k] = f[k] + g - 1.f;                 // diag removed
        g = (g + 1.f) * d[k];
    }
    float2* zp = (float2*)(g_zr + ro);
    #pragma unroll
    for (int k = 0; k < SEG / 2; ++k) zp[k] = make_float2(o[2*k], o[2*k+1]);
}

// ---------------------------------------------------------------------------
// K1: iter-1 column kernel. grid 456+24+24: col tiles | zc tiles | zr groups
// ---------------------------------------------------------------------------
__global__ __launch_bounds__(256) void k_col1(const float* __restrict__ mask,
                                              const float* __restrict__ edge) {
    __shared__ float sm[2 * H * TW];
    float* xs = sm;
    float* ds = sm + H * TW;

    const int bid = blockIdx.x;
    if (bid < NCT) {
        const int jt = bid % (W / TW);
        const int c  = (bid / (W / TW)) % C;
        const int b  = bid / ((W / TW) * C);
        d_prologue(b, jt * TW, edge, ds);
        const float* xg = mask + ((size_t)(b * C + c) * H) * W + jt * TW;
        col_tile_body(b, c, jt * TW, xg, xs, ds);
    } else if (bid < NCT + 24) {
        const int u = bid - NCT;
        d_prologue(u / 6, (u % 6) * TW, edge, ds);
        zc_tile_body(u / 6, (u % 6) * TW, xs, ds);
    } else {
        const int u = bid - NCT - 24;          // [0, 24)
        const int b = u / 6;
        const int lane = threadIdx.x & 31, wid = threadIdx.x >> 5;
        #pragma unroll 1
        for (int q = 0; q < 4; ++q) {
            int i = (u % 6) * TW + wid * 4 + q;   // [0, 192)
            zr_chain(b, i, lane, edge);
        }
    }
}

// ---------------------------------------------------------------------------
// K2: column kernel for iters 2/3 (src from ping-pong)
// ---------------------------------------------------------------------------
__global__ __launch_bounds__(256) void k_col(const float* __restrict__ edge, int src) {
    __shared__ float sm[2 * H * TW];
    float* xs = sm;
    float* ds = sm + H * TW;

    const int bid = blockIdx.x;
    const int jt = bid % (W / TW);
    const int c  = (bid / (W / TW)) % C;
    const int b  = bid / ((W / TW) * C);
    d_prologue(b, jt * TW, edge, ds);
    const float* xg = (src == 1 ? g_featA : g_featB) + ((size_t)(b * C + c) * H) * W + jt * TW;
    col_tile_body(b, c, jt * TW, xg, xs, ds);
}

// ---------------------------------------------------------------------------
// K3: row kernel — TWO channel chains per warp (shared d, z, scan-carry A).
// Unit u in [0, B*H*NPAIR): bi = u/NPAIR -> (b,i); p = u%NPAIR.
// p<9: channels (2p, 2p+1); p==9: (18,18) self-pair (benign duplicate).
// ---------------------------------------------------------------------------
__global__ __launch_bounds__(128) void k_row(const float* __restrict__ xin,
                                             const float* __restrict__ edge,
                                             float* __restrict__ oext,
                                             int src, int dst) {
    const int u = blockIdx.x * 4 + (threadIdx.x >> 5);   // [0, B*H*NPAIR)
    const int lane = threadIdx.x & 31;
    const int bi = u / NPAIR;
    const int p  = u - bi * NPAIR;
    const int b  = bi / H;
    const int i  = bi - b * H;
    const int c0 = 2 * p;
    const int c1 = (c0 + 1 < C) ? c0 + 1 : c0;

    const size_t off0 = ((size_t)(b * C + c0) * H + i) * W + lane * SEG;
    const size_t off1 = ((size_t)(b * C + c1) * H + i) * W + lane * SEG;
    const size_t ro   = (size_t)b * HW + (size_t)i * W + lane * SEG;

    // shared per-pair: decay + normalizer
    const float2* ep = (const float2*)(edge + ro);
    float d[SEG];
    #pragma unroll
    for (int k = 0; k < SEG / 2; ++k) {
        float2 t = ep[k];
        d[2*k]   = exp2f(-THC * fmaxf(t.x, 0.f));
        d[2*k+1] = exp2f(-THC * fmaxf(t.y, 0.f));
    }
    const float2* zcp = (const float2*)(g_zc + ro);
    const float2* zrp = (const float2*)(g_zr + ro);
    float z[SEG];
    #pragma unroll
    for (int k = 0; k < SEG / 2; ++k) {
        float2 tc = zcp[k], tr = zrp[k];
        z[2*k]   = __fdividef(1.f, tc.x + tr.x);
        z[2*k+1] = __fdividef(1.f, tc.y + tr.y);
    }

    // per-channel loads: x and colA (t starts as a)
    const float* xsrc = pick_src(src, xin);
    float x0[SEG], x1[SEG], t0[SEG], t1[SEG];
    {
        const float2* xp0 = (const float2*)(xsrc + off0);
        const float2* xp1 = (const float2*)(xsrc + off1);
        const float2* ap0 = (const float2*)(g_colA + off0);
        const float2* ap1 = (const float2*)(g_colA + off1);
        #pragma unroll
        for (int k = 0; k < SEG / 2; ++k) {
            float2 a = xp0[k]; x0[2*k] = a.x; x0[2*k+1] = a.y;
            float2 bb = xp1[k]; x1[2*k] = bb.x; x1[2*k+1] = bb.y;
            float2 cA = ap0[k]; t0[2*k] = cA.x; t0[2*k+1] = cA.y;
            float2 dA = ap1[k]; t1[2*k] = dA.x; t1[2*k+1] = dA.y;
        }
    }

    // forward scans (shared A)
    float F0 = 0.f, F1 = 0.f, A = 1.f;
    #pragma unroll
    for (int k = 0; k < SEG; ++k) {
        F0 = fmaf(F0, d[k], x0[k]);
        F1 = fmaf(F1, d[k], x1[k]);
        A *= d[k];
    }
    const float As = A;
    wscan_fwd3(A, F0, F1, lane);
    float fin0 = __shfl_up_sync(0xffffffffu, F0, 1);
    float fin1 = __shfl_up_sync(0xffffffffu, F1, 1);
    if (lane == 0) { fin0 = 0.f; fin1 = 0.f; }
    {
        float v0 = fin0, v1 = fin1;
        #pragma unroll
        for (int k = 0; k < SEG; ++k) {
            v0 = fmaf(v0, d[k], x0[k]); t0[k] += v0 - x0[k];   // t = a + f - x
            v1 = fmaf(v1, d[k], x1[k]); t1[k] += v1 - x1[k];
        }
    }

    // backward scans (shared A)
    float G0 = 0.f, G1 = 0.f, Ab = As;
    #pragma unroll
    for (int k = SEG - 1; k >= 0; --k) {
        G0 = (G0 + x0[k]) * d[k];
        G1 = (G1 + x1[k]) * d[k];
    }
    wscan_bwd3(Ab, G0, G1, lane);
    float gin0 = __shfl_down_sync(0xffffffffu, G0, 1);
    float gin1 = __shfl_down_sync(0xffffffffu, G1, 1);
    if (lane == 31) { gin0 = 0.f; gin1 = 0.f; }

    // combine + normalize (o overwrites t)
    {
        float g0 = gin0, g1 = gin1;
        #pragma unroll
        for (int k = SEG - 1; k >= 0; --k) {
            float o0 = (t0[k] + g0) * z[k];
            float o1 = (t1[k] + g1) * z[k];
            g0 = (g0 + x0[k]) * d[k];
            g1 = (g1 + x1[k]) * d[k];
            t0[k] = o0; t1[k] = o1;
        }
    }

    float* ob = (dst == 0) ? oext : (dst == 1 ? g_featA : g_featB);
    float2* op0 = (float2*)(ob + off0);
    float2* op1 = (float2*)(ob + off1);
    #pragma unroll
    for (int k = 0; k < SEG / 2; ++k) {
        op0[k] = make_float2(t0[2*k], t0[2*k+1]);
        op1[k] = make_float2(t1[2*k], t1[2*k+1]);
    }
}

// ---------------------------------------------------------------------------
// iter fixed at 3 by setup_inputs. 6 launches.
// ---------------------------------------------------------------------------
extern "C" void kernel_launch(void* const* d_in, const int* in_sizes, int n_in,
                              void* d_out, int out_size) {
    const float* mask = (const float*)d_in[0];
    const float* edge = (const float*)d_in[1];
    float* out = (float*)d_out;

    const int GR = (B * H * NPAIR) / 4;     // 1920 blocks x 4 warps

    // iter 1 (col kernel also computes zc, zr)
    k_col1<<<NCT + 48, 256>>>(mask, edge);
    k_row<<<GR, 128>>>(mask, edge, nullptr, 0, 1);
    // iter 2
    k_col<<<NCT, 256>>>(edge, 1);
    k_row<<<GR, 128>>>(nullptr, edge, nullptr, 1, 2);
    // iter 3
    k_col<<<NCT, 256>>>(edge, 2);
    k_row<<<GR, 128>>>(nullptr, edge, out, 2, 0);
}

// round 13
// speedup vs baseline: 1.0294x; 1.0209x over previous
#include <cuda_runtime.h>

#define B 4
#define C 19
#define H 192
#define W 192
#define HW (H*W)
// 40 * log2(e): exp(-40*x) == exp2(-THC*x)
#define THC 57.70780163555853f
#define SEG 6          // elements per lane; 32*6 = 192 = chain length
#define TW 32          // column-tile width
#define NCT 456        // col tiles = B*C*(W/TW)
#define NPAIR 10       // channel pair-units per (b,i): 9 pairs + 1 self-pair

// ---------------------------------------------------------------------------
// Static scratch (allocations forbidden)
// ---------------------------------------------------------------------------
__device__ float g_zc  [B*HW];                 // column Z (incl diag), edge-only
__device__ float g_zr  [B*HW];                 // row Z (diag removed), edge-only
__device__ float g_colA[(size_t)B*C*HW];       // column aggregation result
__device__ float g_featA[(size_t)B*C*HW];      // ping
__device__ float g_featB[(size_t)B*C*HW];      // pong

__device__ __forceinline__ const float* pick_src(int s, const float* ext) {
    return s == 0 ? ext : (s == 1 ? g_featA : g_featB);
}

// warp scans of segment transfer (A, F): f_out = A*f_in + F
__device__ __forceinline__ void wscan_fwd(float& A, float& F, int lane) {
    #pragma unroll
    for (int dl = 1; dl < 32; dl <<= 1) {
        float oa = __shfl_up_sync(0xffffffffu, A, dl);
        float of = __shfl_up_sync(0xffffffffu, F, dl);
        if (lane >= dl) { F = fmaf(of, A, F); A = oa * A; }
    }
}
__device__ __forceinline__ void wscan_bwd(float& A, float& G, int lane) {
    #pragma unroll
    for (int dl = 1; dl < 32; dl <<= 1) {
        float oa = __shfl_down_sync(0xffffffffu, A, dl);
        float og = __shfl_down_sync(0xffffffffu, G, dl);
        if (lane < 32 - dl) { G = fmaf(A, og, G); A = oa * A; }
    }
}
// 3-payload versions: two chains share the same A (same d sequence)
__device__ __forceinline__ void wscan_fwd3(float& A, float& F0, float& F1, int lane) {
    #pragma unroll
    for (int dl = 1; dl < 32; dl <<= 1) {
        float oa = __shfl_up_sync(0xffffffffu, A, dl);
        float o0 = __shfl_up_sync(0xffffffffu, F0, dl);
        float o1 = __shfl_up_sync(0xffffffffu, F1, dl);
        if (lane >= dl) { F0 = fmaf(o0, A, F0); F1 = fmaf(o1, A, F1); A = oa * A; }
    }
}
__device__ __forceinline__ void wscan_bwd3(float& A, float& G0, float& G1, int lane) {
    #pragma unroll
    for (int dl = 1; dl < 32; dl <<= 1) {
        float oa = __shfl_down_sync(0xffffffffu, A, dl);
        float o0 = __shfl_down_sync(0xffffffffu, G0, dl);
        float o1 = __shfl_down_sync(0xffffffffu, G1, dl);
        if (lane < 32 - dl) { G0 = fmaf(A, o0, G0); G1 = fmaf(A, o1, G1); A = oa * A; }
    }
}

// ---------------------------------------------------------------------------
// d prologue for a (b, j-tile): edge -> ds (swizzled), float4 global loads
// ---------------------------------------------------------------------------
__device__ __forceinline__ void d_prologue(int b, int j0,
                                           const float* __restrict__ edge,
                                           float* ds) {
    const int tid = threadIdx.x;
    const float* eg = edge + b * HW + j0;
    #pragma unroll
    for (int it = 0; it < 6; ++it) {
        int u = it * 256 + tid;
        int row = u >> 3, g = (u & 7) << 2;
        float4 ev = *(const float4*)(eg + row * W + g);
        int rb = row & 31, s0 = row * TW;
        ds[s0 + ((g + 0) ^ rb)] = exp2f(-THC * fmaxf(ev.x, 0.f));
        ds[s0 + ((g + 1) ^ rb)] = exp2f(-THC * fmaxf(ev.y, 0.f));
        ds[s0 + ((g + 2) ^ rb)] = exp2f(-THC * fmaxf(ev.z, 0.f));
        ds[s0 + ((g + 3) ^ rb)] = exp2f(-THC * fmaxf(ev.w, 0.f));
    }
}

// ---------------------------------------------------------------------------
// Column tile body: stage x (float4), scan 4 cols/warp, write colA (float4)
// ---------------------------------------------------------------------------
__device__ __forceinline__ void col_tile_body(int b, int c, int j0,
                                              const float* __restrict__ xg,
                                              float* xs, float* ds) {
    const int tid = threadIdx.x;
    const int lane = tid & 31, wid = tid >> 5;

    #pragma unroll
    for (int it = 0; it < 6; ++it) {
        int u = it * 256 + tid;
        int row = u >> 3, g = (u & 7) << 2;
        float4 xv = *(const float4*)(xg + (size_t)row * W + g);
        int rb = row & 31, s0 = row * TW;
        xs[s0 + ((g + 0) ^ rb)] = xv.x;
        xs[s0 + ((g + 1) ^ rb)] = xv.y;
        xs[s0 + ((g + 2) ^ rb)] = xv.z;
        xs[s0 + ((g + 3) ^ rb)] = xv.w;
    }
    __syncthreads();

    #pragma unroll
    for (int cc = 0; cc < 4; ++cc) {
        const int jl = wid * 4 + cc;
        float x[SEG], d[SEG];
        #pragma unroll
        for (int k = 0; k < SEG; ++k) {
            int i = lane * SEG + k;
            int sw = i * TW + (jl ^ (i & 31));
            x[k] = xs[sw]; d[k] = ds[sw];
        }

        float F = 0.f, A = 1.f;
        #pragma unroll
        for (int k = 0; k < SEG; ++k) { F = fmaf(F, d[k], x[k]); A *= d[k]; }
        float Af = A;
        wscan_fwd(Af, F, lane);
        float fin = __shfl_up_sync(0xffffffffu, F, 1);
        if (lane == 0) fin = 0.f;
        float f[SEG], v = fin;
        #pragma unroll
        for (int k = 0; k < SEG; ++k) { v = fmaf(v, d[k], x[k]); f[k] = v; }

        float G = 0.f, Ab = A;
        #pragma unroll
        for (int k = SEG - 1; k >= 0; --k) G = (G + x[k]) * d[k];
        wscan_bwd(Ab, G, lane);
        float gin = __shfl_down_sync(0xffffffffu, G, 1);
        if (lane == 31) gin = 0.f;

        float g = gin;
        #pragma unroll
        for (int k = SEG - 1; k >= 0; --k) {
            int i = lane * SEG + k;
            xs[i * TW + (jl ^ (i & 31))] = f[k] + g;
            g = (g + x[k]) * d[k];
        }
    }
    __syncthreads();

    float* ag = g_colA + ((size_t)(b * C + c) * H) * W + j0;
    #pragma unroll
    for (int it = 0; it < 6; ++it) {
        int u = it * 256 + tid;
        int row = u >> 3, g = (u & 7) << 2;
        int rb = row & 31, s0 = row * TW;
        float4 ov;
        ov.x = xs[s0 + ((g + 0) ^ rb)];
        ov.y = xs[s0 + ((g + 1) ^ rb)];
        ov.z = xs[s0 + ((g + 2) ^ rb)];
        ov.w = xs[s0 + ((g + 3) ^ rb)];
        *(float4*)(ag + (size_t)row * W + g) = ov;
    }
}

// ---------------------------------------------------------------------------
// zc tile: ones-scan over staged ds; writeback float4
// ---------------------------------------------------------------------------
__device__ __forceinline__ void zc_tile_body(int b, int j0, float* xs, float* ds) {
    const int tid = threadIdx.x;
    const int lane = tid & 31, wid = tid >> 5;
    __syncthreads();          // ds staged by d_prologue

    #pragma unroll
    for (int cc = 0; cc < 4; ++cc) {
        const int jl = wid * 4 + cc;
        float d[SEG];
        #pragma unroll
        for (int k = 0; k < SEG; ++k) {
            int i = lane * SEG + k;
            d[k] = ds[i * TW + (jl ^ (i & 31))];
        }
        float F = 0.f, A = 1.f;
        #pragma unroll
        for (int k = 0; k < SEG; ++k) { F = fmaf(F, d[k], 1.f); A *= d[k]; }
        float Af = A;
        wscan_fwd(Af, F, lane);
        float fin = __shfl_up_sync(0xffffffffu, F, 1);
        if (lane == 0) fin = 0.f;
        float f[SEG], v = fin;
        #pragma unroll
        for (int k = 0; k < SEG; ++k) { v = fmaf(v, d[k], 1.f); f[k] = v; }

        float G = 0.f, Ab = A;
        #pragma unroll
        for (int k = SEG - 1; k >= 0; --k) G = (G + 1.f) * d[k];
        wscan_bwd(Ab, G, lane);
        float gin = __shfl_down_sync(0xffffffffu, G, 1);
        if (lane == 31) gin = 0.f;

        float g = gin;
        #pragma unroll
        for (int k = SEG - 1; k >= 0; --k) {
            int i = lane * SEG + k;
            xs[i * TW + (jl ^ (i & 31))] = f[k] + g;   // zc incl diag
            g = (g + 1.f) * d[k];
        }
    }
    __syncthreads();

    float* zg = g_zc + b * HW + j0;
    #pragma unroll
    for (int it = 0; it < 6; ++it) {
        int u = it * 256 + tid;
        int row = u >> 3, g = (u & 7) << 2;
        int rb = row & 31, s0 = row * TW;
        float4 ov;
        ov.x = xs[s0 + ((g + 0) ^ rb)];
        ov.y = xs[s0 + ((g + 1) ^ rb)];
        ov.z = xs[s0 + ((g + 2) ^ rb)];
        ov.w = xs[s0 + ((g + 3) ^ rb)];
        *(float4*)(zg + row * W + g) = ov;
    }
}

// ---------------------------------------------------------------------------
// zr chain: edge-only ones-scan along a row (coalesced)
// ---------------------------------------------------------------------------
__device__ __forceinline__ void zr_chain(int b, int i, int lane,
                                         const float* __restrict__ edge) {
    size_t ro = (size_t)b * HW + (size_t)i * W + lane * SEG;
    const float2* ep = (const float2*)(edge + ro);
    float d[SEG];
    #pragma unroll
    for (int k = 0; k < SEG / 2; ++k) {
        float2 t = ep[k];
        d[2*k]   = exp2f(-THC * fmaxf(t.x, 0.f));
        d[2*k+1] = exp2f(-THC * fmaxf(t.y, 0.f));
    }
    float F = 0.f, A = 1.f;
    #pragma unroll
    for (int k = 0; k < SEG; ++k) { F = fmaf(F, d[k], 1.f); A *= d[k]; }
    float Af = A;
    wscan_fwd(Af, F, lane);
    float fin = __shfl_up_sync(0xffffffffu, F, 1);
    if (lane == 0) fin = 0.f;
    float f[SEG], v = fin;
    #pragma unroll
    for (int k = 0; k < SEG; ++k) { v = fmaf(v, d[k], 1.f); f[k] = v; }

    float G = 0.f, Ab = A;
    #pragma unroll
    for (int k = SEG - 1; k >= 0; --k) G = (G + 1.f) * d[k];
    wscan_bwd(Ab, G, lane);
    float gin = __shfl_down_sync(0xffffffffu, G, 1);
    if (lane == 31) gin = 0.f;

    float o[SEG], g = gin;
    #pragma unroll
    for (int k = SEG - 1; k >= 0; --k) {
        o[k] = f[k] + g - 1.f;                 // diag removed
        g = (g + 1.f) * d[k];
    }
    float2* zp = (float2*)(g_zr + ro);
    #pragma unroll
    for (int k = 0; k < SEG / 2; ++k) zp[k] = make_float2(o[2*k], o[2*k+1]);
}

// ---------------------------------------------------------------------------
// K1: iter-1 column kernel. grid 456+24+24: col tiles | zc tiles | zr groups
// ---------------------------------------------------------------------------
__global__ __launch_bounds__(256) void k_col1(const float* __restrict__ mask,
                                              const float* __restrict__ edge) {
    __shared__ float sm[2 * H * TW];
    float* xs = sm;
    float* ds = sm + H * TW;

    const int bid = blockIdx.x;
    if (bid < NCT) {
        const int jt = bid % (W / TW);
        const int c  = (bid / (W / TW)) % C;
        const int b  = bid / ((W / TW) * C);
        d_prologue(b, jt * TW, edge, ds);
        const float* xg = mask + ((size_t)(b * C + c) * H) * W + jt * TW;
        col_tile_body(b, c, jt * TW, xg, xs, ds);
    } else if (bid < NCT + 24) {
        const int u = bid - NCT;
        d_prologue(u / 6, (u % 6) * TW, edge, ds);
        zc_tile_body(u / 6, (u % 6) * TW, xs, ds);
    } else {
        const int u = bid - NCT - 24;          // [0, 24)
        const int b = u / 6;
        const int lane = threadIdx.x & 31, wid = threadIdx.x >> 5;
        #pragma unroll 1
        for (int q = 0; q < 4; ++q) {
            int i = (u % 6) * TW + wid * 4 + q;   // [0, 192)
            zr_chain(b, i, lane, edge);
        }
    }
}

// ---------------------------------------------------------------------------
// K2: column kernel for iters 2/3 (src from ping-pong)
// ---------------------------------------------------------------------------
__global__ __launch_bounds__(256) void k_col(const float* __restrict__ edge, int src) {
    __shared__ float sm[2 * H * TW];
    float* xs = sm;
    float* ds = sm + H * TW;

    const int bid = blockIdx.x;
    const int jt = bid % (W / TW);
    const int c  = (bid / (W / TW)) % C;
    const int b  = bid / ((W / TW) * C);
    d_prologue(b, jt * TW, edge, ds);
    const float* xg = (src == 1 ? g_featA : g_featB) + ((size_t)(b * C + c) * H) * W + jt * TW;
    col_tile_body(b, c, jt * TW, xg, xs, ds);
}

// ---------------------------------------------------------------------------
// K3: row kernel — TWO channel chains per warp (shared d, z, scan-carry A).
// Unit u in [0, B*H*NPAIR): bi = u/NPAIR -> (b,i); p = u%NPAIR.
// p<9: channels (2p, 2p+1); p==9: (18,18) self-pair (benign duplicate).
// ---------------------------------------------------------------------------
__global__ __launch_bounds__(128) void k_row(const float* __restrict__ xin,
                                             const float* __restrict__ edge,
                                             float* __restrict__ oext,
                                             int src, int dst) {
    const int u = blockIdx.x * 4 + (threadIdx.x >> 5);   // [0, B*H*NPAIR)
    const int lane = threadIdx.x & 31;
    const int bi = u / NPAIR;
    const int p  = u - bi * NPAIR;
    const int b  = bi / H;
    const int i  = bi - b * H;
    const int c0 = 2 * p;
    const int c1 = (c0 + 1 < C) ? c0 + 1 : c0;

    const size_t off0 = ((size_t)(b * C + c0) * H + i) * W + lane * SEG;
    const size_t off1 = ((size_t)(b * C + c1) * H + i) * W + lane * SEG;
    const size_t ro   = (size_t)b * HW + (size_t)i * W + lane * SEG;

    // shared per-pair: decay + normalizer
    const float2* ep = (const float2*)(edge + ro);
    float d[SEG];
    #pragma unroll
    for (int k = 0; k < SEG / 2; ++k) {
        float2 t = ep[k];
        d[2*k]   = exp2f(-THC * fmaxf(t.x, 0.f));
        d[2*k+1] = exp2f(-THC * fmaxf(t.y, 0.f));
    }
    const float2* zcp = (const float2*)(g_zc + ro);
    const float2* zrp = (const float2*)(g_zr + ro);
    float z[SEG];
    #pragma unroll
    for (int k = 0; k < SEG / 2; ++k) {
        float2 tc = zcp[k], tr = zrp[k];
        z[2*k]   = __fdividef(1.f, tc.x + tr.x);
        z[2*k+1] = __fdividef(1.f, tc.y + tr.y);
    }

    // per-channel loads: x and colA (t starts as a)
    const float* xsrc = pick_src(src, xin);
    float x0[SEG], x1[SEG], t0[SEG], t1[SEG];
    {
        const float2* xp0 = (const float2*)(xsrc + off0);
        const float2* xp1 = (const float2*)(xsrc + off1);
        const float2* ap0 = (const float2*)(g_colA + off0);
        const float2* ap1 = (const float2*)(g_colA + off1);
        #pragma unroll
        for (int k = 0; k < SEG / 2; ++k) {
            float2 a = xp0[k]; x0[2*k] = a.x; x0[2*k+1] = a.y;
            float2 bb = xp1[k]; x1[2*k] = bb.x; x1[2*k+1] = bb.y;
            float2 cA = ap0[k]; t0[2*k] = cA.x; t0[2*k+1] = cA.y;
            float2 dA = ap1[k]; t1[2*k] = dA.x; t1[2*k+1] = dA.y;
        }
    }

    // forward scans (shared A)
    float F0 = 0.f, F1 = 0.f, A = 1.f;
    #pragma unroll
    for (int k = 0; k < SEG; ++k) {
        F0 = fmaf(F0, d[k], x0[k]);
        F1 = fmaf(F1, d[k], x1[k]);
        A *= d[k];
    }
    const float As = A;
    wscan_fwd3(A, F0, F1, lane);
    float fin0 = __shfl_up_sync(0xffffffffu, F0, 1);
    float fin1 = __shfl_up_sync(0xffffffffu, F1, 1);
    if (lane == 0) { fin0 = 0.f; fin1 = 0.f; }
    {
        float v0 = fin0, v1 = fin1;
        #pragma unroll
        for (int k = 0; k < SEG; ++k) {
            v0 = fmaf(v0, d[k], x0[k]); t0[k] += v0 - x0[k];   // t = a + f - x
            v1 = fmaf(v1, d[k], x1[k]); t1[k] += v1 - x1[k];
        }
    }

    // backward scans (shared A)
    float G0 = 0.f, G1 = 0.f, Ab = As;
    #pragma unroll
    for (int k = SEG - 1; k >= 0; --k) {
        G0 = (G0 + x0[k]) * d[k];
        G1 = (G1 + x1[k]) * d[k];
    }
    wscan_bwd3(Ab, G0, G1, lane);
    float gin0 = __shfl_down_sync(0xffffffffu, G0, 1);
    float gin1 = __shfl_down_sync(0xffffffffu, G1, 1);
    if (lane == 31) { gin0 = 0.f; gin1 = 0.f; }

    // combine + normalize (o overwrites t)
    {
        float g0 = gin0, g1 = gin1;
        #pragma unroll
        for (int k = SEG - 1; k >= 0; --k) {
            float o0 = (t0[k] + g0) * z[k];
            float o1 = (t1[k] + g1) * z[k];
            g0 = (g0 + x0[k]) * d[k];
            g1 = (g1 + x1[k]) * d[k];
            t0[k] = o0; t1[k] = o1;
        }
    }

    float* ob = (dst == 0) ? oext : (dst == 1 ? g_featA : g_featB);
    float2* op0 = (float2*)(ob + off0);
    float2* op1 = (float2*)(ob + off1);
    #pragma unroll
    for (int k = 0; k < SEG / 2; ++k) {
        op0[k] = make_float2(t0[2*k], t0[2*k+1]);
        op1[k] = make_float2(t1[2*k], t1[2*k+1]);
    }
}

// ---------------------------------------------------------------------------
// iter fixed at 3 by setup_inputs. 6 launches.
// ---------------------------------------------------------------------------
extern "C" void kernel_launch(void* const* d_in, const int* in_sizes, int n_in,
                              void* d_out, int out_size) {
    const float* mask = (const float*)d_in[0];
    const float* edge = (const float*)d_in[1];
    float* out = (float*)d_out;

    const int GR = (B * H * NPAIR) / 4;     // 1920 blocks x 4 warps

    // iter 1 (col kernel also computes zc, zr)
    k_col1<<<NCT + 48, 256>>>(mask, edge);
    k_row<<<GR, 128>>>(mask, edge, nullptr, 0, 1);
    // iter 2
    k_col<<<NCT, 256>>>(edge, 1);
    k_row<<<GR, 128>>>(nullptr, edge, nullptr, 1, 2);
    // iter 3
    k_col<<<NCT, 256>>>(edge, 2);
    k_row<<<GR, 128>>>(nullptr, edge, out, 2, 0);
}